// round 7
// baseline (speedup 1.0000x reference)
#include <cuda_runtime.h>
#include <math.h>

#define A_N 8192
#define K_N 64
#define D_N 128
#define B_N 16384
#define GRID_N (A_N + B_N / 4)

// Scratch: per-anchor npair losses [0, A_N) and per-row norms [A_N, A_N+B_N).
__device__ float g_part[A_N + B_N];
// Completion counter for last-block final reduction (reset each launch by last block).
__device__ unsigned int g_count;

__device__ __forceinline__ int load_idx(const void* p, long long i, int is64) {
    return is64 ? (int)((const long long*)p)[i] : ((const int*)p)[i];
}

// Merge two multi-dot partial registers at lane-distance s:
// 1 shuffle + selects instead of 2 full butterflies.
__device__ __forceinline__ float merge2(float x, float y, int s, int lane) {
    float send = (lane & s) ? x : y;
    float keep = (lane & s) ? y : x;
    float t = __shfl_xor_sync(0xffffffffu, send, s);
    return keep + t;
}

// RELEASE-only atomic increment at gpu scope. Release orders this block's
// prior global stores (L1 is write-through, so release needs NO CCTL.IVALL).
// Acquire-flavored ops (__threadfence, atom.acq_rel) invalidate the whole L1D
// so that subsequent plain loads see remote writes -- that flush, once per
// block, is what destroyed the gather's L1 reuse in R5/R6.
__device__ __forceinline__ unsigned int atom_inc_release(unsigned int* p) {
    unsigned int old;
    asm volatile("atom.release.gpu.global.add.u32 %0, [%1], %2;"
                 : "=r"(old) : "l"(p), "r"(1u) : "memory");
    return old;
}

// Cache-bypassing float4 load (always fresh from L2) for the final reduction;
// the single reader block needs no acquire fence (and thus no L1 flush).
__device__ __forceinline__ float4 ldcv4(const float4* p) {
    float4 v;
    asm volatile("ld.global.cv.v4.f32 {%0,%1,%2,%3}, [%4];"
                 : "=f"(v.x), "=f"(v.y), "=f"(v.z), "=f"(v.w)
                 : "l"(p) : "memory");
    return v;
}

// ---------------------------------------------------------------------------
// Single fused kernel:
//   blocks [0, A_N): one block (4 warps) per anchor -> N-pair loss term.
//   blocks [A_N, GRID_N): per-row L2 norms, 4 rows per block.
//   last block to finish: deterministic final reduction -> out[0].
// Index dtype (int32 vs int64) detected per-warp from the block's own slice of
// neg_ind: indices < 16384, so under little-endian int64 all odd 32-bit words
// are zero; under int32 they are random indices (P(all 32 zero) ~ 1e-135).
// ---------------------------------------------------------------------------
__global__ __launch_bounds__(128) void fused_kernel(
    const float* __restrict__ E,
    const void* __restrict__ anc,
    const void* __restrict__ pos,
    const void* __restrict__ neg,
    float* __restrict__ out)
{
    const int t = threadIdx.x;
    const int w = t >> 5;
    const int l = t & 31;

    __shared__ float sA[D_N];
    __shared__ float sRed[4];
    __shared__ float sM[4], sS[4];
    __shared__ unsigned int sLast;

    if (blockIdx.x >= A_N) {
        // ---- L2 norms: one warp per row ----
        const int row = (blockIdx.x - A_N) * 4 + w;
        const float4 v = ((const float4*)(E + (long long)row * D_N))[l];
        float s = v.x * v.x + v.y * v.y + v.z * v.z + v.w * v.w;
        #pragma unroll
        for (int o = 16; o; o >>= 1) s += __shfl_xor_sync(0xffffffffu, s, o);
        if (l == 0) sRed[w] = sqrtf(s);
        __syncthreads();
        if (t == 0) {
            const int rb = A_N + (blockIdx.x - A_N) * 4;
            g_part[rb + 0] = sRed[0];
            g_part[rb + 1] = sRed[1];
            g_part[rb + 2] = sRed[2];
            g_part[rb + 3] = sRed[3];
        }
    } else {
        const int a = blockIdx.x;

        // ---- per-warp dtype detection (1 LDG + 5 shuffles) ----
        unsigned int det = ((const unsigned int*)neg)[a * 64 + 2 * l + 1];
        #pragma unroll
        for (int o = 16; o; o >>= 1) det |= __shfl_xor_sync(0xffffffffu, det, o);
        const int is64 = (det == 0u) ? 1 : 0;

        const int ai = load_idx(anc, a, is64);
        const int pi = load_idx(pos, a, is64);

        const float av = E[(long long)ai * D_N + t];
        const float pv = E[(long long)pi * D_N + t];
        sA[t] = av;

        // Block-reduce a.p (computed once, subtracted as a scalar)
        float ap = av * pv;
        #pragma unroll
        for (int o = 16; o; o >>= 1) ap += __shfl_xor_sync(0xffffffffu, ap, o);
        if (l == 0) sRed[w] = ap;
        __syncthreads();
        const float apf = sRed[0] + sRed[1] + sRed[2] + sRed[3];

        const float4 a4 = ((const float4*)sA)[l];

        // ---- 16 negatives per warp; coalesced float4 gathers, front-batched ----
        const long long kbase = (long long)a * K_N + (long long)w * 16;
        float d[16];
        #pragma unroll
        for (int j = 0; j < 16; j++) {
            const long long nidx = (long long)load_idx(neg, kbase + j, is64);
            const float4 v = __ldg((const float4*)(E + nidx * D_N) + l);
            d[j] = v.x * a4.x + v.y * a4.y + v.z * a4.z + v.w * a4.w;
        }

        // ---- merge-tree reduce: 16 dots x 32 lanes in 16 shuffles ----
        float e[8], f[4], g[2], h;
        #pragma unroll
        for (int m = 0; m < 8; m++) e[m] = merge2(d[2 * m], d[2 * m + 1], 16, l);
        #pragma unroll
        for (int m = 0; m < 4; m++) f[m] = merge2(e[2 * m], e[2 * m + 1], 8, l);
        #pragma unroll
        for (int m = 0; m < 2; m++) g[m] = merge2(f[2 * m], f[2 * m + 1], 4, l);
        h = merge2(g[0], g[1], 2, l);
        h += __shfl_xor_sync(0xffffffffu, h, 1);
        const float inner = h - apf;  // lane l holds dot k(l), duplicated x2

        // ---- in-warp logsumexp over this warp's 16 dots ----
        float m1 = inner;
        #pragma unroll
        for (int o = 16; o; o >>= 1) m1 = fmaxf(m1, __shfl_xor_sync(0xffffffffu, m1, o));
        float s1 = __expf(inner - m1);
        #pragma unroll
        for (int o = 16; o; o >>= 1) s1 += __shfl_xor_sync(0xffffffffu, s1, o);
        if (l == 0) { sM[w] = m1; sS[w] = 0.5f * s1; }  // halve: duplicates
        __syncthreads();

        if (t == 0) {
            float M = fmaxf(fmaxf(sM[0], sM[1]), fmaxf(sM[2], sM[3]));
            float S = sS[0] * __expf(sM[0] - M) + sS[1] * __expf(sM[1] - M)
                    + sS[2] * __expf(sM[2] - M) + sS[3] * __expf(sM[3] - M);
            const float lse = M + logf(S);
            g_part[a] = fmaxf(lse, 0.0f) + log1pf(expf(-fabsf(lse)));
        }
    }

    // ---- completion handshake: release-only (no L1D flush anywhere) ----
    __syncthreads();
    if (t == 0) {
        const unsigned int old = atom_inc_release(&g_count);
        sLast = (old == (unsigned int)(GRID_N - 1)) ? 1u : 0u;
    }
    __syncthreads();
    if (sLast) {
        // Reader side: .cv loads bypass L1 -> no acquire needed.
        const float invA = 1.0f / (float)A_N;
        const float cB   = 0.25f / (float)B_N;
        const float4* p4 = (const float4*)g_part;
        float accA = 0.0f, accB = 0.0f;
        #pragma unroll 4
        for (int i = t; i < A_N / 4; i += 128) {
            const float4 v = ldcv4(p4 + i);
            accA += (v.x + v.y) + (v.z + v.w);
        }
        #pragma unroll 4
        for (int i = A_N / 4 + t; i < (A_N + B_N) / 4; i += 128) {
            const float4 v = ldcv4(p4 + i);
            accB += (v.x + v.y) + (v.z + v.w);
        }
        float acc = accA * invA + accB * cB;
        #pragma unroll
        for (int o = 16; o; o >>= 1) acc += __shfl_xor_sync(0xffffffffu, acc, o);
        if (l == 0) sRed[w] = acc;
        __syncthreads();
        if (t == 0) {
            out[0] = sRed[0] + sRed[1] + sRed[2] + sRed[3];
            g_count = 0u;  // reset for next graph replay
        }
    }
}

extern "C" void kernel_launch(void* const* d_in, const int* in_sizes, int n_in,
                              void* d_out, int out_size) {
    const float* E   = (const float*)d_in[0];   // image_embed [B, D] f32
    const void*  anc = d_in[1];                 // anc_ind [A]
    const void*  pos = d_in[2];                 // pos_ind [A]
    const void*  neg = d_in[3];                 // neg_ind [A, K]
    float* out = (float*)d_out;

    fused_kernel<<<GRID_N, 128>>>(E, anc, pos, neg, out);
}

// round 8
// speedup vs baseline: 1.2342x; 1.2342x over previous
#include <cuda_runtime.h>
#include <math.h>

#define A_N 8192
#define K_N 64
#define D_N 128
#define B_N 16384

// Scratch: per-anchor npair losses [0, A_N) and per-row norms [A_N, A_N+B_N).
__device__ float g_part[A_N + B_N];

__device__ __forceinline__ int load_idx(const void* p, long long i, int is64) {
    return is64 ? (int)((const long long*)p)[i] : ((const int*)p)[i];
}

// Merge two multi-dot partial registers at lane-distance s:
// 1 shuffle + selects instead of 2 full butterflies.
__device__ __forceinline__ float merge2(float x, float y, int s, int lane) {
    float send = (lane & s) ? x : y;
    float keep = (lane & s) ? y : x;
    float t = __shfl_xor_sync(0xffffffffu, send, s);
    return keep + t;
}

// ---------------------------------------------------------------------------
// Fused compute kernel (R3 structure):
//   blocks [0, A_N): one block (4 warps) per anchor -> N-pair loss term.
//   blocks [A_N, A_N + B_N/4): per-row L2 norms, 4 rows per block.
// Index dtype (int32 vs int64) detected per-warp from the block's own slice of
// neg_ind: indices < 16384, so under little-endian int64 all odd 32-bit words
// are zero; under int32 they are random indices (P(all 32 zero) ~ 1e-135).
// NO terminal handshake, NO in-kernel final reduction -- isolating the R5-R7
// regression to that machinery.
// ---------------------------------------------------------------------------
__global__ __launch_bounds__(128) void fused_kernel(
    const float* __restrict__ E,
    const void* __restrict__ anc,
    const void* __restrict__ pos,
    const void* __restrict__ neg)
{
    const int t = threadIdx.x;
    const int w = t >> 5;
    const int l = t & 31;

    if (blockIdx.x >= A_N) {
        // ---- L2 norms: one warp per row ----
        const int row = (blockIdx.x - A_N) * 4 + w;
        const float4 v = ((const float4*)(E + (long long)row * D_N))[l];
        float s = v.x * v.x + v.y * v.y + v.z * v.z + v.w * v.w;
        #pragma unroll
        for (int o = 16; o; o >>= 1) s += __shfl_xor_sync(0xffffffffu, s, o);
        if (l == 0) g_part[A_N + row] = sqrtf(s);
        return;
    }

    __shared__ float sA[D_N];
    __shared__ float sRed[4];
    __shared__ float sM[4], sS[4];

    const int a = blockIdx.x;

    // ---- per-warp dtype detection (1 LDG + 5 shuffles) ----
    unsigned int det = ((const unsigned int*)neg)[a * 64 + 2 * l + 1];
    #pragma unroll
    for (int o = 16; o; o >>= 1) det |= __shfl_xor_sync(0xffffffffu, det, o);
    const int is64 = (det == 0u) ? 1 : 0;

    const int ai = load_idx(anc, a, is64);
    const int pi = load_idx(pos, a, is64);

    const float av = E[(long long)ai * D_N + t];
    const float pv = E[(long long)pi * D_N + t];
    sA[t] = av;

    // Block-reduce a.p (computed once, subtracted as a scalar)
    float ap = av * pv;
    #pragma unroll
    for (int o = 16; o; o >>= 1) ap += __shfl_xor_sync(0xffffffffu, ap, o);
    if (l == 0) sRed[w] = ap;
    __syncthreads();
    const float apf = sRed[0] + sRed[1] + sRed[2] + sRed[3];

    const float4 a4 = ((const float4*)sA)[l];

    // ---- 16 negatives per warp; coalesced float4 gathers, front-batched ----
    const long long kbase = (long long)a * K_N + (long long)w * 16;
    float d[16];
    #pragma unroll
    for (int j = 0; j < 16; j++) {
        const long long nidx = (long long)load_idx(neg, kbase + j, is64);
        const float4 v = __ldg((const float4*)(E + nidx * D_N) + l);
        d[j] = v.x * a4.x + v.y * a4.y + v.z * a4.z + v.w * a4.w;
    }

    // ---- merge-tree reduce: 16 dots x 32 lanes in 16 shuffles ----
    float e[8], f[4], g[2], h;
    #pragma unroll
    for (int m = 0; m < 8; m++) e[m] = merge2(d[2 * m], d[2 * m + 1], 16, l);
    #pragma unroll
    for (int m = 0; m < 4; m++) f[m] = merge2(e[2 * m], e[2 * m + 1], 8, l);
    #pragma unroll
    for (int m = 0; m < 2; m++) g[m] = merge2(f[2 * m], f[2 * m + 1], 4, l);
    h = merge2(g[0], g[1], 2, l);
    h += __shfl_xor_sync(0xffffffffu, h, 1);
    const float inner = h - apf;  // lane l holds dot k(l), duplicated x2

    // ---- in-warp logsumexp over this warp's 16 dots ----
    float m1 = inner;
    #pragma unroll
    for (int o = 16; o; o >>= 1) m1 = fmaxf(m1, __shfl_xor_sync(0xffffffffu, m1, o));
    float s1 = __expf(inner - m1);
    #pragma unroll
    for (int o = 16; o; o >>= 1) s1 += __shfl_xor_sync(0xffffffffu, s1, o);
    if (l == 0) { sM[w] = m1; sS[w] = 0.5f * s1; }  // halve: duplicates
    __syncthreads();

    if (t == 0) {
        float M = fmaxf(fmaxf(sM[0], sM[1]), fmaxf(sM[2], sM[3]));
        float S = sS[0] * __expf(sM[0] - M) + sS[1] * __expf(sM[1] - M)
                + sS[2] * __expf(sM[2] - M) + sS[3] * __expf(sM[3] - M);
        const float lse = M + logf(S);
        g_part[a] = fmaxf(lse, 0.0f) + log1pf(expf(-fabsf(lse)));
    }
}

// ---------------------------------------------------------------------------
// Deterministic final reduction (single block, fixed order, float4 loads).
// out = mean(per_anchor) + 0.25 * mean(norms)
// ---------------------------------------------------------------------------
__global__ void final_kernel(float* __restrict__ out) {
    __shared__ float s[32];
    const float invA = 1.0f / (float)A_N;
    const float cB   = 0.25f / (float)B_N;
    const float4* __restrict__ p4 = (const float4*)g_part;
    float accA = 0.0f, accB = 0.0f;
    for (int i = threadIdx.x; i < A_N / 4; i += blockDim.x) {
        const float4 v = p4[i];
        accA += (v.x + v.y) + (v.z + v.w);
    }
    for (int i = A_N / 4 + threadIdx.x; i < (A_N + B_N) / 4; i += blockDim.x) {
        const float4 v = p4[i];
        accB += (v.x + v.y) + (v.z + v.w);
    }
    float acc = accA * invA + accB * cB;
    #pragma unroll
    for (int o = 16; o; o >>= 1) acc += __shfl_xor_sync(0xffffffffu, acc, o);
    const int w = threadIdx.x >> 5, l = threadIdx.x & 31;
    if (l == 0) s[w] = acc;
    __syncthreads();
    if (threadIdx.x == 0) {
        float r = 0.0f;
        const int nw = (int)(blockDim.x >> 5);
        for (int i = 0; i < nw; i++) r += s[i];
        out[0] = r;
    }
}

extern "C" void kernel_launch(void* const* d_in, const int* in_sizes, int n_in,
                              void* d_out, int out_size) {
    const float* E   = (const float*)d_in[0];   // image_embed [B, D] f32
    const void*  anc = d_in[1];                 // anc_ind [A]
    const void*  pos = d_in[2];                 // pos_ind [A]
    const void*  neg = d_in[3];                 // neg_ind [A, K]
    float* out = (float*)d_out;

    fused_kernel<<<A_N + B_N / 4, 128>>>(E, anc, pos, neg);
    final_kernel<<<1, 1024>>>(out);
}

// round 11
// speedup vs baseline: 1.3995x; 1.1339x over previous
#include <cuda_runtime.h>
#include <cuda_fp16.h>
#include <math.h>

#define A_N 8192
#define K_N 64
#define D_N 128
#define B_N 16384
#define P_N (A_N + B_N / 4)   // compact prescaled partials

// fp16 shadow of the embedding table: 16384 rows x 128 halves = 4.19 MB.
// Row r occupies g_Eh[r*32 .. r*32+31], lane l holds halves [4l..4l+3].
__device__ uint2 g_Eh[B_N * 32];
// Prescaled partials: [0,A_N) anchor losses * (1/A_N); [A_N,P_N) block norm sums * (0.25/B_N).
__device__ float g_part[P_N];

__device__ __forceinline__ unsigned int h2_as_u32(__half2 h) {
    return *reinterpret_cast<unsigned int*>(&h);
}
__device__ __forceinline__ __half2 u32_as_h2(unsigned int u) {
    return *reinterpret_cast<__half2*>(&u);
}

__device__ __forceinline__ int load_idx(const void* p, long long i, int is64) {
    return is64 ? (int)((const long long*)p)[i] : ((const int*)p)[i];
}

// Merge two multi-dot partial registers at lane-distance s (1 shuffle + selects).
__device__ __forceinline__ float merge2(float x, float y, int s, int lane) {
    float send = (lane & s) ? x : y;
    float keep = (lane & s) ? y : x;
    float t = __shfl_xor_sync(0xffffffffu, send, s);
    return keep + t;
}

// ---------------------------------------------------------------------------
// Convert E -> fp16 table, and compute per-row L2 norms on the way (free:
// every row is read here anyway). One warp per row, 4 rows per block.
// ---------------------------------------------------------------------------
__global__ __launch_bounds__(128) void convert_kernel(const float* __restrict__ E) {
    __shared__ float sN[4];
    const int w = threadIdx.x >> 5;
    const int l = threadIdx.x & 31;
    const int row = blockIdx.x * 4 + w;

    const float4 v = ((const float4*)(E + (long long)row * D_N))[l];

    uint2 u;
    u.x = h2_as_u32(__floats2half2_rn(v.x, v.y));
    u.y = h2_as_u32(__floats2half2_rn(v.z, v.w));
    g_Eh[row * 32 + l] = u;

    float s = v.x * v.x + v.y * v.y + v.z * v.z + v.w * v.w;
    #pragma unroll
    for (int o = 16; o; o >>= 1) s += __shfl_xor_sync(0xffffffffu, s, o);
    if (l == 0) sN[w] = sqrtf(s);
    __syncthreads();
    if (threadIdx.x == 0)
        g_part[A_N + blockIdx.x] = (sN[0] + sN[1] + sN[2] + sN[3]) * (0.25f / (float)B_N);
}

// ---------------------------------------------------------------------------
// N-pair kernel: one block (4 warps) per anchor. Gathers are fp16 rows
// (256B/warp-load -> half the LTS traffic of fp32). a.p stays fp32.
// Index dtype detected per-warp as before.
// ---------------------------------------------------------------------------
__global__ __launch_bounds__(128) void npair_kernel(
    const float* __restrict__ E,
    const void* __restrict__ anc,
    const void* __restrict__ pos,
    const void* __restrict__ neg)
{
    __shared__ float sRed[4];
    __shared__ float sM[4], sS[4];

    const int t = threadIdx.x;
    const int w = t >> 5;
    const int l = t & 31;
    const int a = blockIdx.x;

    // ---- per-warp dtype detection (1 LDG + 5 shuffles) ----
    unsigned int det = ((const unsigned int*)neg)[a * 64 + 2 * l + 1];
    #pragma unroll
    for (int o = 16; o; o >>= 1) det |= __shfl_xor_sync(0xffffffffu, det, o);
    const int is64 = (det == 0u) ? 1 : 0;

    const int ai = load_idx(anc, a, is64);
    const int pi = load_idx(pos, a, is64);

    // ---- a.p in fp32 (one element per thread) ----
    const float av = E[(long long)ai * D_N + t];
    const float pv = E[(long long)pi * D_N + t];
    float ap = av * pv;
    #pragma unroll
    for (int o = 16; o; o >>= 1) ap += __shfl_xor_sync(0xffffffffu, ap, o);
    if (l == 0) sRed[w] = ap;
    __syncthreads();
    const float apf = sRed[0] + sRed[1] + sRed[2] + sRed[3];

    // ---- anchor row from fp16 table: lane l holds halves [4l..4l+3] ----
    const uint2 au = g_Eh[ai * 32 + l];
    const float2 a01 = __half22float2(u32_as_h2(au.x));
    const float2 a23 = __half22float2(u32_as_h2(au.y));

    // ---- 16 negatives per warp; fp16 gathers (256B/warp-load) ----
    const long long kbase = (long long)a * K_N + (long long)w * 16;
    float d[16];
    #pragma unroll
    for (int j = 0; j < 16; j++) {
        const int nidx = load_idx(neg, kbase + j, is64);
        const uint2 nu = __ldg(&g_Eh[nidx * 32 + l]);
        const float2 n01 = __half22float2(u32_as_h2(nu.x));
        const float2 n23 = __half22float2(u32_as_h2(nu.y));
        d[j] = a01.x * n01.x + a01.y * n01.y + a23.x * n23.x + a23.y * n23.y;
    }

    // ---- merge-tree reduce: 16 dots x 32 lanes in 16 shuffles ----
    float e[8], f[4], g[2], h;
    #pragma unroll
    for (int m = 0; m < 8; m++) e[m] = merge2(d[2 * m], d[2 * m + 1], 16, l);
    #pragma unroll
    for (int m = 0; m < 4; m++) f[m] = merge2(e[2 * m], e[2 * m + 1], 8, l);
    #pragma unroll
    for (int m = 0; m < 2; m++) g[m] = merge2(f[2 * m], f[2 * m + 1], 4, l);
    h = merge2(g[0], g[1], 2, l);
    h += __shfl_xor_sync(0xffffffffu, h, 1);
    const float inner = h - apf;  // lane l holds dot k(l), duplicated x2

    // ---- in-warp logsumexp over this warp's 16 dots ----
    float m1 = inner;
    #pragma unroll
    for (int o = 16; o; o >>= 1) m1 = fmaxf(m1, __shfl_xor_sync(0xffffffffu, m1, o));
    float s1 = __expf(inner - m1);
    #pragma unroll
    for (int o = 16; o; o >>= 1) s1 += __shfl_xor_sync(0xffffffffu, s1, o);
    if (l == 0) { sM[w] = m1; sS[w] = 0.5f * s1; }  // halve: duplicates
    __syncthreads();

    if (t == 0) {
        float M = fmaxf(fmaxf(sM[0], sM[1]), fmaxf(sM[2], sM[3]));
        float S = sS[0] * __expf(sM[0] - M) + sS[1] * __expf(sM[1] - M)
                + sS[2] * __expf(sM[2] - M) + sS[3] * __expf(sM[3] - M);
        const float lse = M + logf(S);
        const float pa = fmaxf(lse, 0.0f) + log1pf(expf(-fabsf(lse)));
        g_part[a] = pa * (1.0f / (float)A_N);
    }
}

// ---------------------------------------------------------------------------
// Deterministic final reduction: all partials prescaled -> uniform sum.
// 12288 floats, single block, fixed order.
// ---------------------------------------------------------------------------
__global__ void final_kernel(float* __restrict__ out) {
    __shared__ float s[32];
    const float4* __restrict__ p4 = (const float4*)g_part;
    float acc = 0.0f;
    #pragma unroll
    for (int i = threadIdx.x; i < P_N / 4; i += 1024) {
        const float4 v = p4[i];
        acc += (v.x + v.y) + (v.z + v.w);
    }
    #pragma unroll
    for (int o = 16; o; o >>= 1) acc += __shfl_xor_sync(0xffffffffu, acc, o);
    const int w = threadIdx.x >> 5, l = threadIdx.x & 31;
    if (l == 0) s[w] = acc;
    __syncthreads();
    if (threadIdx.x == 0) {
        float r = 0.0f;
        for (int i = 0; i < 32; i++) r += s[i];
        out[0] = r;
    }
}

extern "C" void kernel_launch(void* const* d_in, const int* in_sizes, int n_in,
                              void* d_out, int out_size) {
    const float* E   = (const float*)d_in[0];   // image_embed [B, D] f32
    const void*  anc = d_in[1];                 // anc_ind [A]
    const void*  pos = d_in[2];                 // pos_ind [A]
    const void*  neg = d_in[3];                 // neg_ind [A, K]
    float* out = (float*)d_out;

    convert_kernel<<<B_N / 4, 128>>>(E);
    npair_kernel<<<A_N, 128>>>(E, anc, pos, neg);
    final_kernel<<<1, 1024>>>(out);
}

// round 15
// speedup vs baseline: 1.5727x; 1.1237x over previous
#include <cuda_runtime.h>
#include <cuda_fp16.h>
#include <math.h>

#define A_N 8192
#define K_N 64
#define D_N 128
#define B_N 16384
#define CVT_BLOCKS 1024              // 16 rows per block
#define P_N (A_N + CVT_BLOCKS)       // compact prescaled partials

// fp16 shadow of the embedding table: 16384 rows x 128 halves = 4.19 MB.
// Row r occupies g_Eh[r*32 .. r*32+31], lane l holds halves [4l..4l+3].
__device__ uint2 g_Eh[B_N * 32];
// Prescaled partials: [0,A_N) anchor losses * (1/A_N); [A_N,P_N) block norm sums * (0.25/B_N).
__device__ float g_part[P_N];

__device__ __forceinline__ unsigned int h2_as_u32(__half2 h) {
    return *reinterpret_cast<unsigned int*>(&h);
}
__device__ __forceinline__ __half2 u32_as_h2(unsigned int u) {
    return *reinterpret_cast<__half2*>(&u);
}

__device__ __forceinline__ int load_idx(const void* p, long long i, int is64) {
    return is64 ? (int)((const long long*)p)[i] : ((const int*)p)[i];
}

// Merge two multi-value partial registers at lane-distance s (1 shuffle + selects):
// lanes with (lane&s)==0 end holding x reduced over {l,l^s}; others y reduced.
__device__ __forceinline__ float merge2(float x, float y, int s, int lane) {
    float send = (lane & s) ? x : y;
    float keep = (lane & s) ? y : x;
    float t = __shfl_xor_sync(0xffffffffu, send, s);
    return keep + t;
}

// ---------------------------------------------------------------------------
// Convert E -> fp16 table + per-row L2 norms. 256 threads/block, each warp
// handles 2 rows (independent front-batched loads for MLP). Both norms
// reduced in ONE 5-shuffle pass: merge at 16 splits rows into lane halves,
// butterflies 8/4/2/1 finish each half. 16 rows/block -> 1 prescaled partial.
// ---------------------------------------------------------------------------
__global__ __launch_bounds__(256) void convert_kernel(const float* __restrict__ E) {
    __shared__ float sN[16];
    const int w = threadIdx.x >> 5;      // warp 0..7
    const int l = threadIdx.x & 31;
    const int row0 = blockIdx.x * 16 + w * 2;
    const int row1 = row0 + 1;

    const float4 v0 = ((const float4*)(E + (long long)row0 * D_N))[l];
    const float4 v1 = ((const float4*)(E + (long long)row1 * D_N))[l];

    uint2 u0, u1;
    u0.x = h2_as_u32(__floats2half2_rn(v0.x, v0.y));
    u0.y = h2_as_u32(__floats2half2_rn(v0.z, v0.w));
    u1.x = h2_as_u32(__floats2half2_rn(v1.x, v1.y));
    u1.y = h2_as_u32(__floats2half2_rn(v1.z, v1.w));
    g_Eh[row0 * 32 + l] = u0;
    g_Eh[row1 * 32 + l] = u1;

    float n0 = v0.x * v0.x + v0.y * v0.y + v0.z * v0.z + v0.w * v0.w;
    float n1 = v1.x * v1.x + v1.y * v1.y + v1.z * v1.z + v1.w * v1.w;
    float s = merge2(n0, n1, 16, l);     // low lanes: row0 partial; high: row1
    #pragma unroll
    for (int o = 8; o; o >>= 1) s += __shfl_xor_sync(0xffffffffu, s, o);
    if (l == 0)  sN[w * 2 + 0] = sqrtf(s);   // lane 0 holds full row0 sum
    if (l == 16) sN[w * 2 + 1] = sqrtf(s);   // lane 16 holds full row1 sum
    __syncthreads();
    if (threadIdx.x == 0) {
        float t = 0.0f;
        #pragma unroll
        for (int i = 0; i < 16; i++) t += sN[i];
        g_part[A_N + blockIdx.x] = t * (0.25f / (float)B_N);
    }
}

// ---------------------------------------------------------------------------
// N-pair kernel: one block (4 warps) per anchor. ALL row reads from the fp16
// table. NOTE: with lane l holding elements [4l..4l+3], EACH WARP computes the
// FULL a.p by itself after its butterfly (no cross-warp sum! summing the 4
// warp values would give 4*a.p -- the R12 bug).
// ---------------------------------------------------------------------------
__global__ __launch_bounds__(128) void npair_kernel(
    const void* __restrict__ anc,
    const void* __restrict__ pos,
    const void* __restrict__ neg)
{
    __shared__ float sM[4], sS[4];

    const int t = threadIdx.x;
    const int w = t >> 5;
    const int l = t & 31;
    const int a = blockIdx.x;

    // ---- per-warp dtype detection (1 LDG + 5 shuffles) ----
    unsigned int det = ((const unsigned int*)neg)[a * 64 + 2 * l + 1];
    #pragma unroll
    for (int o = 16; o; o >>= 1) det |= __shfl_xor_sync(0xffffffffu, det, o);
    const int is64 = (det == 0u) ? 1 : 0;

    const int ai = load_idx(anc, a, is64);
    const int pi = load_idx(pos, a, is64);

    // ---- anchor + positive rows from fp16 table ----
    const uint2 au = g_Eh[ai * 32 + l];
    const uint2 pu = g_Eh[pi * 32 + l];
    const float2 a01 = __half22float2(u32_as_h2(au.x));
    const float2 a23 = __half22float2(u32_as_h2(au.y));
    const float2 p01 = __half22float2(u32_as_h2(pu.x));
    const float2 p23 = __half22float2(u32_as_h2(pu.y));

    // ---- a.p: warp-local butterfly gives the FULL dot in every lane ----
    float apf = a01.x * p01.x + a01.y * p01.y + a23.x * p23.x + a23.y * p23.y;
    #pragma unroll
    for (int o = 16; o; o >>= 1) apf += __shfl_xor_sync(0xffffffffu, apf, o);

    // ---- 16 negatives per warp; fp16 gathers (256B/warp-load) ----
    const long long kbase = (long long)a * K_N + (long long)w * 16;
    float d[16];
    #pragma unroll
    for (int j = 0; j < 16; j++) {
        const int nidx = load_idx(neg, kbase + j, is64);
        const uint2 nu = __ldg(&g_Eh[nidx * 32 + l]);
        const float2 n01 = __half22float2(u32_as_h2(nu.x));
        const float2 n23 = __half22float2(u32_as_h2(nu.y));
        d[j] = a01.x * n01.x + a01.y * n01.y + a23.x * n23.x + a23.y * n23.y;
    }

    // ---- merge-tree reduce: 16 dots x 32 lanes in 16 shuffles ----
    float e[8], f[4], g[2], h;
    #pragma unroll
    for (int m = 0; m < 8; m++) e[m] = merge2(d[2 * m], d[2 * m + 1], 16, l);
    #pragma unroll
    for (int m = 0; m < 4; m++) f[m] = merge2(e[2 * m], e[2 * m + 1], 8, l);
    #pragma unroll
    for (int m = 0; m < 2; m++) g[m] = merge2(f[2 * m], f[2 * m + 1], 4, l);
    h = merge2(g[0], g[1], 2, l);
    h += __shfl_xor_sync(0xffffffffu, h, 1);
    const float inner = h - apf;  // lane l holds dot k(l), duplicated x2

    // ---- in-warp logsumexp over this warp's 16 dots ----
    float m1 = inner;
    #pragma unroll
    for (int o = 16; o; o >>= 1) m1 = fmaxf(m1, __shfl_xor_sync(0xffffffffu, m1, o));
    float s1 = __expf(inner - m1);
    #pragma unroll
    for (int o = 16; o; o >>= 1) s1 += __shfl_xor_sync(0xffffffffu, s1, o);
    if (l == 0) { sM[w] = m1; sS[w] = 0.5f * s1; }  // halve: duplicates
    __syncthreads();

    if (t == 0) {
        float M = fmaxf(fmaxf(sM[0], sM[1]), fmaxf(sM[2], sM[3]));
        float S = sS[0] * __expf(sM[0] - M) + sS[1] * __expf(sM[1] - M)
                + sS[2] * __expf(sM[2] - M) + sS[3] * __expf(sM[3] - M);
        const float lse = M + logf(S);
        const float pa = fmaxf(lse, 0.0f) + log1pf(expf(-fabsf(lse)));
        g_part[a] = pa * (1.0f / (float)A_N);
    }
}

// ---------------------------------------------------------------------------
// Deterministic final reduction: all partials prescaled -> uniform sum.
// 9216 floats, single block, fixed order.
// ---------------------------------------------------------------------------
__global__ void final_kernel(float* __restrict__ out) {
    __shared__ float s[32];
    const float4* __restrict__ p4 = (const float4*)g_part;
    float acc = 0.0f;
    for (int i = threadIdx.x; i < P_N / 4; i += 1024) {
        const float4 v = p4[i];
        acc += (v.x + v.y) + (v.z + v.w);
    }
    #pragma unroll
    for (int o = 16; o; o >>= 1) acc += __shfl_xor_sync(0xffffffffu, acc, o);
    const int w = threadIdx.x >> 5, l = threadIdx.x & 31;
    if (l == 0) s[w] = acc;
    __syncthreads();
    if (threadIdx.x == 0) {
        float r = 0.0f;
        for (int i = 0; i < 32; i++) r += s[i];
        out[0] = r;
    }
}

extern "C" void kernel_launch(void* const* d_in, const int* in_sizes, int n_in,
                              void* d_out, int out_size) {
    const float* E   = (const float*)d_in[0];   // image_embed [B, D] f32
    const void*  anc = d_in[1];                 // anc_ind [A]
    const void*  pos = d_in[2];                 // pos_ind [A]
    const void*  neg = d_in[3];                 // neg_ind [A, K]
    float* out = (float*)d_out;

    convert_kernel<<<CVT_BLOCKS, 256>>>(E);
    npair_kernel<<<A_N, 128>>>(anc, pos, neg);
    final_kernel<<<1, 1024>>>(out);
}